// round 6
// baseline (speedup 1.0000x reference)
#include <cuda_runtime.h>
#include <cuda_bf16.h>
#include <cstdint>

// Problem constants
#define NN 8192
#define RR 32
#define TN 128                    // M-tile per block
#define SPLITK 8
#define KCHUNK (NN / SPLITK)      // 1024
#define KT 32                     // fp32 K per stage
#define NSTG (KCHUNK / KT)        // 32

// Scratch
__device__ float g_z[4 * RR * NN];          // z stages [k][r][n]
__device__ float g_part[SPLITK * RR * NN];  // split-K partials

// smem byte offsets (static 40KB)
#define SM_AHI 0
#define SM_ALO 16384
#define SM_BHI 32768
#define SM_BLO 36864
#define SM_TOTAL 40960
#define A_BUF 8192                // per double-buffer: 128 rows x 32 bf16 (64B rows)
#define B_BUF 2048                // 32 rows x 32 bf16

__device__ __forceinline__ uint32_t swz64(uint32_t o) { return o ^ ((o >> 3) & 0x30); }

__device__ __forceinline__ uint32_t cvt_bf16x2(float hi, float lo) {
    uint32_t r;
    asm("cvt.rn.bf16x2.f32 %0,%1,%2;" : "=r"(r) : "f"(hi), "f"(lo));
    return r;
}
// split 2 fp32 -> packed bf16 hi-pair and lo-pair (element x in low half)
__device__ __forceinline__ void split2(float x, float y, uint32_t& w, uint32_t& l) {
    w = cvt_bf16x2(y, x);
    float h0 = __uint_as_float(w << 16);
    float h1 = __uint_as_float(w & 0xFFFF0000u);
    l = cvt_bf16x2(y - h1, x - h0);
}
__device__ __forceinline__ void ldsm4(uint32_t& r0, uint32_t& r1, uint32_t& r2,
                                      uint32_t& r3, uint32_t a) {
    asm volatile("ldmatrix.sync.aligned.m8n8.x4.shared.b16 {%0,%1,%2,%3},[%4];"
                 : "=r"(r0), "=r"(r1), "=r"(r2), "=r"(r3) : "r"(a));
}
__device__ __forceinline__ void mma16816(float& c0, float& c1, float& c2, float& c3,
                                         uint32_t a0, uint32_t a1, uint32_t a2, uint32_t a3,
                                         uint32_t b0, uint32_t b1) {
    asm volatile(
        "mma.sync.aligned.m16n8k16.row.col.f32.bf16.bf16.f32 "
        "{%0,%1,%2,%3},{%4,%5,%6,%7},{%8,%9},{%0,%1,%2,%3};"
        : "+f"(c0), "+f"(c1), "+f"(c2), "+f"(c3)
        : "r"(a0), "r"(a1), "r"(a2), "r"(a3), "r"(b0), "r"(b1));
}

// ---------------------------------------------------------------------------
// Stage 0: transpose x[B,N,G] -> z0[r][n], r = b*8+g
// ---------------------------------------------------------------------------
__global__ void transpose_kernel(const float* __restrict__ x, float* __restrict__ z0) {
    int idx = blockIdx.x * 256 + threadIdx.x;
    int n = idx & (NN - 1);
    int r = idx >> 13;
    int b = r >> 3;
    int g = r & 7;
    z0[idx] = x[((b << 13) + n) * 8 + g];
}

// ---------------------------------------------------------------------------
// bf16x3 mma.sync GEMM: part[sp][r][n0+m] = sum_{k in chunk} S[n0+m][k] * z[r][k]
// 256 threads / 8 warps; warp w owns M-rows 16w..16w+15, all 32 N.
// ---------------------------------------------------------------------------
__global__ void __launch_bounds__(256, 2)
gemm_kernel(const float* __restrict__ A, const float* __restrict__ B,
            float* __restrict__ part) {
    __shared__ __align__(128) char sm[SM_TOTAL];
    const uint32_t smb = (uint32_t)__cvta_generic_to_shared(sm);

    const int tid = threadIdx.x;
    const int wid = tid >> 5;
    const int lid = tid & 31;
    const int nb  = blockIdx.x;   // 0..63
    const int sp  = blockIdx.y;   // 0..SPLITK-1
    const int n0  = nb * TN;
    const int m0  = sp * KCHUNK;

    // LDG mapping: 32 rows x 8 quads covers a 32-row slab; A uses 4 slabs (p)
    const int arow = tid >> 3;            // 0..31
    const int acq  = (tid & 7) << 2;      // fp32 col 0,4,...,28
    const float* Ab = A + (size_t)(n0 + arow) * NN + m0 + acq;
    const float* Bb = B + (size_t)arow * NN + m0 + acq;
    const uint32_t sts_boff = swz64((uint32_t)arow * 64u + (uint32_t)acq * 2u);

    // ldmatrix lane offsets
    const int arow_l = 16 * wid + (lid & 7) + ((lid >> 3) & 1) * 8;
    const int ahalf  = (lid >> 4);                      // 0/1 -> k byte halves
    const int brow0  = ((lid >> 4) << 3) + (lid & 7);   // n-tiles 0/1
    const int brow1  = 16 + brow0;                      // n-tiles 2/3
    const int bhalf  = (lid >> 3) & 1;
    uint32_t aoff[2], boff0[2], boff1[2];
#pragma unroll
    for (int kk = 0; kk < 2; kk++) {
        aoff[kk]  = swz64((uint32_t)arow_l * 64u + kk * 32u + ahalf * 16u);
        boff0[kk] = swz64((uint32_t)brow0 * 64u + kk * 32u + bhalf * 16u);
        boff1[kk] = swz64((uint32_t)brow1 * 64u + kk * 32u + bhalf * 16u);
    }

    float c[4][4];
#pragma unroll
    for (int j = 0; j < 4; j++)
#pragma unroll
        for (int e = 0; e < 4; e++) c[j][e] = 0.0f;

    // register double buffers for global loads
    float4 aR[2][4];
    float4 bR[2];
#pragma unroll
    for (int p = 0; p < 4; p++)
        aR[0][p] = *(const float4*)(Ab + (size_t)(32 * p) * NN);
    bR[0] = *(const float4*)(Bb);

    for (int s = 0; s < NSTG; s++) {
        const int cur = s & 1;

        // prefetch next stage into the other register set
        if (s + 1 < NSTG) {
            const int mc = (s + 1) * KT;
#pragma unroll
            for (int p = 0; p < 4; p++)
                aR[cur ^ 1][p] = *(const float4*)(Ab + (size_t)(32 * p) * NN + mc);
            bR[cur ^ 1] = *(const float4*)(Bb + mc);
        }

        // convert + STS (bf16 hi / lo)
        {
            char* AH = sm + SM_AHI + cur * A_BUF;
            char* AL = sm + SM_ALO + cur * A_BUF;
#pragma unroll
            for (int p = 0; p < 4; p++) {
                float4 v = aR[cur][p];
                uint32_t w01, l01, w23, l23;
                split2(v.x, v.y, w01, l01);
                split2(v.z, v.w, w23, l23);
                uint32_t off = swz64((uint32_t)(arow + 32 * p) * 64u + (uint32_t)acq * 2u);
                *(uint2*)(AH + off) = make_uint2(w01, w23);
                *(uint2*)(AL + off) = make_uint2(l01, l23);
            }
            float4 v = bR[cur];
            uint32_t w01, l01, w23, l23;
            split2(v.x, v.y, w01, l01);
            split2(v.z, v.w, w23, l23);
            *(uint2*)(sm + SM_BHI + cur * B_BUF + sts_boff) = make_uint2(w01, w23);
            *(uint2*)(sm + SM_BLO + cur * B_BUF + sts_boff) = make_uint2(l01, l23);
        }

        __syncthreads();   // single barrier per stage (double buffer makes it sufficient)

        const uint32_t ah_base = smb + SM_AHI + cur * A_BUF;
        const uint32_t al_base = smb + SM_ALO + cur * A_BUF;
        const uint32_t bh_base = smb + SM_BHI + cur * B_BUF;
        const uint32_t bl_base = smb + SM_BLO + cur * B_BUF;

#pragma unroll
        for (int kk = 0; kk < 2; kk++) {
            uint32_t ah0, ah1, ah2, ah3, al0, al1, al2, al3;
            ldsm4(ah0, ah1, ah2, ah3, ah_base + aoff[kk]);
            ldsm4(al0, al1, al2, al3, al_base + aoff[kk]);
            uint32_t bh[8], bl[8];
            ldsm4(bh[0], bh[1], bh[2], bh[3], bh_base + boff0[kk]);
            ldsm4(bh[4], bh[5], bh[6], bh[7], bh_base + boff1[kk]);
            ldsm4(bl[0], bl[1], bl[2], bl[3], bl_base + boff0[kk]);
            ldsm4(bl[4], bl[5], bl[6], bl[7], bl_base + boff1[kk]);
#pragma unroll
            for (int j = 0; j < 4; j++) {
                mma16816(c[j][0], c[j][1], c[j][2], c[j][3],
                         ah0, ah1, ah2, ah3, bh[2 * j], bh[2 * j + 1]);
                mma16816(c[j][0], c[j][1], c[j][2], c[j][3],
                         ah0, ah1, ah2, ah3, bl[2 * j], bl[2 * j + 1]);
                mma16816(c[j][0], c[j][1], c[j][2], c[j][3],
                         al0, al1, al2, al3, bh[2 * j], bh[2 * j + 1]);
            }
        }
    }

    // epilogue: c[j]: thread holds (m = 16w + lid/4 (+8), n = 8j + (lid%4)*2 (+1))
    const int mg = n0 + 16 * wid + (lid >> 2);
#pragma unroll
    for (int j = 0; j < 4; j++) {
        int r = 8 * j + ((lid & 3) << 1);
        float* p0 = part + (size_t)(sp * RR + r) * NN + mg;
        float* p1 = part + (size_t)(sp * RR + r + 1) * NN + mg;
        p0[0] = c[j][0];
        p1[0] = c[j][1];
        p0[8] = c[j][2];
        p1[8] = c[j][3];
    }
}

// ---------------------------------------------------------------------------
// Reduce split-K partials into next z stage
// ---------------------------------------------------------------------------
__global__ void reduce_kernel(const float* __restrict__ part, float* __restrict__ out) {
    int idx = blockIdx.x * 256 + threadIdx.x;   // over 65536 float4
    const float4* p4 = (const float4*)part;
    float4 s = p4[idx];
#pragma unroll
    for (int sI = 1; sI < SPLITK; sI++) {
        float4 t = p4[idx + sI * (RR * NN / 4)];
        s.x += t.x; s.y += t.y; s.z += t.z; s.w += t.w;
    }
    ((float4*)out)[idx] = s;
}

// ---------------------------------------------------------------------------
// Final projection (torch-faithful raw-reshape mapping)
// ---------------------------------------------------------------------------
__global__ void final_kernel(const float* __restrict__ z, const float* __restrict__ W,
                             const float* __restrict__ bias, float* __restrict__ y) {
    __shared__ float Ws[256];
    __shared__ float bs[8];
    int t = threadIdx.x;
    Ws[t] = W[t];
    if (t < 8) bs[t] = bias[t];
    __syncthreads();

    int idx = blockIdx.x * 256 + t;
    int n = idx & (NN - 1);
    int b = idx >> 13;
    int k0 = n >> 11;
    int g0 = (n >> 8) & 7;
    const float* zp = z + ((size_t)(k0 * RR + b * 8 + g0) << 13) + ((n & 255) << 5);

    float bb = bs[n >> 10];
    float acc[8];
#pragma unroll
    for (int f = 0; f < 8; f++) acc[f] = bb;

#pragma unroll
    for (int jq = 0; jq < 8; jq++) {
        float4 zv = *(const float4*)(zp + 4 * jq);
#pragma unroll
        for (int e = 0; e < 4; e++) {
            float zs = (e == 0) ? zv.x : (e == 1) ? zv.y : (e == 2) ? zv.z : zv.w;
            int j = 4 * jq + e;
#pragma unroll
            for (int f = 0; f < 8; f++) acc[f] += zs * Ws[8 * j + f];
        }
    }

    float4* yo = (float4*)(y + (size_t)idx * 8);
    yo[0] = make_float4(acc[0], acc[1], acc[2], acc[3]);
    yo[1] = make_float4(acc[4], acc[5], acc[6], acc[7]);
}

// ---------------------------------------------------------------------------
extern "C" void kernel_launch(void* const* d_in, const int* in_sizes, int n_in,
                              void* d_out, int out_size) {
    const float* x    = (const float*)d_in[0];
    const float* S    = (const float*)d_in[1];
    const float* W    = (const float*)d_in[2];
    const float* bias = (const float*)d_in[3];
    float* y = (float*)d_out;

    float *zbuf, *pbuf;
    cudaGetSymbolAddress((void**)&zbuf, g_z);
    cudaGetSymbolAddress((void**)&pbuf, g_part);

    transpose_kernel<<<1024, 256>>>(x, zbuf);

    for (int k = 0; k < 3; k++) {
        gemm_kernel<<<dim3(64, SPLITK), 256>>>(S + (size_t)k * NN * NN,
                                               zbuf + (size_t)k * RR * NN, pbuf);
        reduce_kernel<<<256, 256>>>(pbuf, zbuf + (size_t)(k + 1) * RR * NN);
    }

    final_kernel<<<128, 256>>>(zbuf, W, bias, y);
}

// round 7
// speedup vs baseline: 1.2190x; 1.2190x over previous
#include <cuda_runtime.h>
#include <cuda_bf16.h>
#include <cstdint>

// Problem constants
#define NN 8192
#define RR 32
#define TN 128                    // M-tile per block
#define SPLITK 16
#define KCHUNK (NN / SPLITK)      // 512
#define KT 32                     // fp32 K per stage
#define NSTG (KCHUNK / KT)        // 16

// Scratch
__device__ float g_z[4 * RR * NN];          // z stages [k][r][n]
__device__ float g_part[SPLITK * RR * NN];  // split-K partials (16 MB)

// smem byte offsets (static 40KB)
#define SM_AHI 0
#define SM_ALO 16384
#define SM_BHI 32768
#define SM_BLO 36864
#define SM_TOTAL 40960
#define A_BUF 8192                // per double-buffer: 128 rows x 32 bf16 (64B rows)
#define B_BUF 2048                // 32 rows x 32 bf16

__device__ __forceinline__ uint32_t swz64(uint32_t o) { return o ^ ((o >> 3) & 0x30); }

__device__ __forceinline__ uint32_t cvt_bf16x2(float hi, float lo) {
    uint32_t r;
    asm("cvt.rn.bf16x2.f32 %0,%1,%2;" : "=r"(r) : "f"(hi), "f"(lo));
    return r;
}
// split 2 fp32 -> packed bf16 hi-pair and lo-pair (element x in low half)
__device__ __forceinline__ void split2(float x, float y, uint32_t& w, uint32_t& l) {
    w = cvt_bf16x2(y, x);
    float h0 = __uint_as_float(w << 16);
    float h1 = __uint_as_float(w & 0xFFFF0000u);
    l = cvt_bf16x2(y - h1, x - h0);
}
__device__ __forceinline__ void ldsm4(uint32_t& r0, uint32_t& r1, uint32_t& r2,
                                      uint32_t& r3, uint32_t a) {
    asm volatile("ldmatrix.sync.aligned.m8n8.x4.shared.b16 {%0,%1,%2,%3},[%4];"
                 : "=r"(r0), "=r"(r1), "=r"(r2), "=r"(r3) : "r"(a));
}
__device__ __forceinline__ void mma16816(float& c0, float& c1, float& c2, float& c3,
                                         uint32_t a0, uint32_t a1, uint32_t a2, uint32_t a3,
                                         uint32_t b0, uint32_t b1) {
    asm volatile(
        "mma.sync.aligned.m16n8k16.row.col.f32.bf16.bf16.f32 "
        "{%0,%1,%2,%3},{%4,%5,%6,%7},{%8,%9},{%0,%1,%2,%3};"
        : "+f"(c0), "+f"(c1), "+f"(c2), "+f"(c3)
        : "r"(a0), "r"(a1), "r"(a2), "r"(a3), "r"(b0), "r"(b1));
}

// ---------------------------------------------------------------------------
// Stage 0: transpose x[B,N,G] -> z0[r][n], r = b*8+g
// ---------------------------------------------------------------------------
__global__ void transpose_kernel(const float* __restrict__ x, float* __restrict__ z0) {
    int idx = blockIdx.x * 256 + threadIdx.x;
    int n = idx & (NN - 1);
    int r = idx >> 13;
    int b = r >> 3;
    int g = r & 7;
    z0[idx] = x[((b << 13) + n) * 8 + g];
}

// ---------------------------------------------------------------------------
// bf16x3 mma.sync GEMM: part[sp][r][n0+m] = sum_{k in chunk} S[n0+m][k] * z[r][k]
// 256 threads / 8 warps; warp w owns M-rows 16w..16w+15, all 32 N.
// ---------------------------------------------------------------------------
__global__ void __launch_bounds__(256, 2)
gemm_kernel(const float* __restrict__ A, const float* __restrict__ B,
            float* __restrict__ part) {
    __shared__ __align__(128) char sm[SM_TOTAL];
    const uint32_t smb = (uint32_t)__cvta_generic_to_shared(sm);

    const int tid = threadIdx.x;
    const int wid = tid >> 5;
    const int lid = tid & 31;
    const int nb  = blockIdx.x;   // 0..63
    const int sp  = blockIdx.y;   // 0..SPLITK-1
    const int n0  = nb * TN;
    const int m0  = sp * KCHUNK;

    // LDG mapping: 32 rows x 8 quads covers a 32-row slab; A uses 4 slabs (p)
    const int arow = tid >> 3;            // 0..31
    const int acq  = (tid & 7) << 2;      // fp32 col 0,4,...,28
    const float* Ab = A + (size_t)(n0 + arow) * NN + m0 + acq;
    const float* Bb = B + (size_t)arow * NN + m0 + acq;
    const uint32_t sts_boff = swz64((uint32_t)arow * 64u + (uint32_t)acq * 2u);

    // ldmatrix lane offsets
    const int arow_l = 16 * wid + (lid & 7) + ((lid >> 3) & 1) * 8;
    const int ahalf  = (lid >> 4);                      // 0/1 -> k byte halves
    const int brow0  = ((lid >> 4) << 3) + (lid & 7);   // n-tiles 0/1
    const int brow1  = 16 + brow0;                      // n-tiles 2/3
    const int bhalf  = (lid >> 3) & 1;
    uint32_t aoff[2], boff0[2], boff1[2];
#pragma unroll
    for (int kk = 0; kk < 2; kk++) {
        aoff[kk]  = swz64((uint32_t)arow_l * 64u + kk * 32u + ahalf * 16u);
        boff0[kk] = swz64((uint32_t)brow0 * 64u + kk * 32u + bhalf * 16u);
        boff1[kk] = swz64((uint32_t)brow1 * 64u + kk * 32u + bhalf * 16u);
    }

    float c[4][4];
#pragma unroll
    for (int j = 0; j < 4; j++)
#pragma unroll
        for (int e = 0; e < 4; e++) c[j][e] = 0.0f;

    // register double buffers for global loads
    float4 aR[2][4];
    float4 bR[2];
#pragma unroll
    for (int p = 0; p < 4; p++)
        aR[0][p] = *(const float4*)(Ab + (size_t)(32 * p) * NN);
    bR[0] = *(const float4*)(Bb);

    for (int s = 0; s < NSTG; s++) {
        const int cur = s & 1;

        // prefetch next stage into the other register set
        if (s + 1 < NSTG) {
            const int mc = (s + 1) * KT;
#pragma unroll
            for (int p = 0; p < 4; p++)
                aR[cur ^ 1][p] = *(const float4*)(Ab + (size_t)(32 * p) * NN + mc);
            bR[cur ^ 1] = *(const float4*)(Bb + mc);
        }

        // convert + STS (bf16 hi / lo)
        {
            char* AH = sm + SM_AHI + cur * A_BUF;
            char* AL = sm + SM_ALO + cur * A_BUF;
#pragma unroll
            for (int p = 0; p < 4; p++) {
                float4 v = aR[cur][p];
                uint32_t w01, l01, w23, l23;
                split2(v.x, v.y, w01, l01);
                split2(v.z, v.w, w23, l23);
                uint32_t off = swz64((uint32_t)(arow + 32 * p) * 64u + (uint32_t)acq * 2u);
                *(uint2*)(AH + off) = make_uint2(w01, w23);
                *(uint2*)(AL + off) = make_uint2(l01, l23);
            }
            float4 v = bR[cur];
            uint32_t w01, l01, w23, l23;
            split2(v.x, v.y, w01, l01);
            split2(v.z, v.w, w23, l23);
            *(uint2*)(sm + SM_BHI + cur * B_BUF + sts_boff) = make_uint2(w01, w23);
            *(uint2*)(sm + SM_BLO + cur * B_BUF + sts_boff) = make_uint2(l01, l23);
        }

        __syncthreads();   // single barrier per stage (double buffer makes it sufficient)

        const uint32_t ah_base = smb + SM_AHI + cur * A_BUF;
        const uint32_t al_base = smb + SM_ALO + cur * A_BUF;
        const uint32_t bh_base = smb + SM_BHI + cur * B_BUF;
        const uint32_t bl_base = smb + SM_BLO + cur * B_BUF;

#pragma unroll
        for (int kk = 0; kk < 2; kk++) {
            uint32_t ah0, ah1, ah2, ah3, al0, al1, al2, al3;
            ldsm4(ah0, ah1, ah2, ah3, ah_base + aoff[kk]);
            ldsm4(al0, al1, al2, al3, al_base + aoff[kk]);
            uint32_t bh[8], bl[8];
            ldsm4(bh[0], bh[1], bh[2], bh[3], bh_base + boff0[kk]);
            ldsm4(bh[4], bh[5], bh[6], bh[7], bh_base + boff1[kk]);
            ldsm4(bl[0], bl[1], bl[2], bl[3], bl_base + boff0[kk]);
            ldsm4(bl[4], bl[5], bl[6], bl[7], bl_base + boff1[kk]);
#pragma unroll
            for (int j = 0; j < 4; j++) {
                mma16816(c[j][0], c[j][1], c[j][2], c[j][3],
                         ah0, ah1, ah2, ah3, bh[2 * j], bh[2 * j + 1]);
                mma16816(c[j][0], c[j][1], c[j][2], c[j][3],
                         ah0, ah1, ah2, ah3, bl[2 * j], bl[2 * j + 1]);
                mma16816(c[j][0], c[j][1], c[j][2], c[j][3],
                         al0, al1, al2, al3, bh[2 * j], bh[2 * j + 1]);
            }
        }
    }

    // epilogue: c[j]: thread holds (m = 16w + lid/4 (+8), n = 8j + (lid%4)*2 (+1))
    const int mg = n0 + 16 * wid + (lid >> 2);
#pragma unroll
    for (int j = 0; j < 4; j++) {
        int r = 8 * j + ((lid & 3) << 1);
        float* p0 = part + (size_t)(sp * RR + r) * NN + mg;
        float* p1 = part + (size_t)(sp * RR + r + 1) * NN + mg;
        p0[0] = c[j][0];
        p1[0] = c[j][1];
        p0[8] = c[j][2];
        p1[8] = c[j][3];
    }
}

// ---------------------------------------------------------------------------
// Reduce split-K partials into next z stage
// ---------------------------------------------------------------------------
__global__ void reduce_kernel(const float* __restrict__ part, float* __restrict__ out) {
    int idx = blockIdx.x * 256 + threadIdx.x;   // over 65536 float4
    const float4* p4 = (const float4*)part;
    float4 s = p4[idx];
#pragma unroll
    for (int sI = 1; sI < SPLITK; sI++) {
        float4 t = p4[idx + sI * (RR * NN / 4)];
        s.x += t.x; s.y += t.y; s.z += t.z; s.w += t.w;
    }
    ((float4*)out)[idx] = s;
}

// ---------------------------------------------------------------------------
// Final projection (torch-faithful raw-reshape mapping)
// ---------------------------------------------------------------------------
__global__ void final_kernel(const float* __restrict__ z, const float* __restrict__ W,
                             const float* __restrict__ bias, float* __restrict__ y) {
    __shared__ float Ws[256];
    __shared__ float bs[8];
    int t = threadIdx.x;
    Ws[t] = W[t];
    if (t < 8) bs[t] = bias[t];
    __syncthreads();

    int idx = blockIdx.x * 256 + t;
    int n = idx & (NN - 1);
    int b = idx >> 13;
    int k0 = n >> 11;
    int g0 = (n >> 8) & 7;
    const float* zp = z + ((size_t)(k0 * RR + b * 8 + g0) << 13) + ((n & 255) << 5);

    float bb = bs[n >> 10];
    float acc[8];
#pragma unroll
    for (int f = 0; f < 8; f++) acc[f] = bb;

#pragma unroll
    for (int jq = 0; jq < 8; jq++) {
        float4 zv = *(const float4*)(zp + 4 * jq);
#pragma unroll
        for (int e = 0; e < 4; e++) {
            float zs = (e == 0) ? zv.x : (e == 1) ? zv.y : (e == 2) ? zv.z : zv.w;
            int j = 4 * jq + e;
#pragma unroll
            for (int f = 0; f < 8; f++) acc[f] += zs * Ws[8 * j + f];
        }
    }

    float4* yo = (float4*)(y + (size_t)idx * 8);
    yo[0] = make_float4(acc[0], acc[1], acc[2], acc[3]);
    yo[1] = make_float4(acc[4], acc[5], acc[6], acc[7]);
}

// ---------------------------------------------------------------------------
extern "C" void kernel_launch(void* const* d_in, const int* in_sizes, int n_in,
                              void* d_out, int out_size) {
    const float* x    = (const float*)d_in[0];
    const float* S    = (const float*)d_in[1];
    const float* W    = (const float*)d_in[2];
    const float* bias = (const float*)d_in[3];
    float* y = (float*)d_out;

    float *zbuf, *pbuf;
    cudaGetSymbolAddress((void**)&zbuf, g_z);
    cudaGetSymbolAddress((void**)&pbuf, g_part);

    transpose_kernel<<<1024, 256>>>(x, zbuf);

    for (int k = 0; k < 3; k++) {
        gemm_kernel<<<dim3(64, SPLITK), 256>>>(S + (size_t)k * NN * NN,
                                               zbuf + (size_t)k * RR * NN, pbuf);
        reduce_kernel<<<256, 256>>>(pbuf, zbuf + (size_t)(k + 1) * RR * NN);
    }

    final_kernel<<<128, 256>>>(zbuf, W, bias, y);
}

// round 8
// speedup vs baseline: 1.2639x; 1.0368x over previous
#include <cuda_runtime.h>
#include <cuda_bf16.h>
#include <cstdint>

// Problem constants
#define NN 8192
#define RR 32
#define TN 128                    // M-tile per block
#define SPLITK 16
#define KCHUNK (NN / SPLITK)      // 512
#define NK16 (KCHUNK / 16)        // 32 k16-steps per CTA

// Scratch
__device__ float g_z[4 * RR * NN];          // z stages [k][r][n]
__device__ float g_part[SPLITK * RR * NN];  // split-K partials (16 MB)

__device__ __forceinline__ uint32_t cvt_bf16x2(float hi, float lo) {
    uint32_t r;
    asm("cvt.rn.bf16x2.f32 %0,%1,%2;" : "=r"(r) : "f"(hi), "f"(lo));
    return r;
}
// split 2 fp32 -> packed bf16 hi-pair and lo-pair (element x in low half)
__device__ __forceinline__ void split2(float x, float y, uint32_t& w, uint32_t& l) {
    w = cvt_bf16x2(y, x);
    float h0 = __uint_as_float(w << 16);
    float h1 = __uint_as_float(w & 0xFFFF0000u);
    l = cvt_bf16x2(y - h1, x - h0);
}
__device__ __forceinline__ void mma16816(float& c0, float& c1, float& c2, float& c3,
                                         uint32_t a0, uint32_t a1, uint32_t a2, uint32_t a3,
                                         uint32_t b0, uint32_t b1) {
    asm volatile(
        "mma.sync.aligned.m16n8k16.row.col.f32.bf16.bf16.f32 "
        "{%0,%1,%2,%3},{%4,%5,%6,%7},{%8,%9},{%0,%1,%2,%3};"
        : "+f"(c0), "+f"(c1), "+f"(c2), "+f"(c3)
        : "r"(a0), "r"(a1), "r"(a2), "r"(a3), "r"(b0), "r"(b1));
}

// ---------------------------------------------------------------------------
// Stage 0: transpose x[B,N,G] -> z0[r][n], r = b*8+g
// ---------------------------------------------------------------------------
__global__ void transpose_kernel(const float* __restrict__ x, float* __restrict__ z0) {
    int idx = blockIdx.x * 256 + threadIdx.x;
    int n = idx & (NN - 1);
    int r = idx >> 13;
    int b = r >> 3;
    int g = r & 7;
    z0[idx] = x[((b << 13) + n) * 8 + g];
}

// ---------------------------------------------------------------------------
// bf16x3 mma.sync GEMM, barrier-free / smem-free:
// part[sp][r][n0+m] = sum_{k in chunk} S[n0+m][k] * z[r][k]
// 256 threads / 8 warps; warp w owns M-rows 16w..16w+15, all 32 N.
// A and B fragments are loaded directly from global as float2 (coalesced
// 32B sectors), split to bf16 hi/lo in registers, fed straight to mma.sync.
// ---------------------------------------------------------------------------
__global__ void __launch_bounds__(256, 3)
gemm_kernel(const float* __restrict__ A, const float* __restrict__ B,
            float* __restrict__ part) {
    const int tid = threadIdx.x;
    const int wid = tid >> 5;
    const int lid = tid & 31;
    const int nb  = blockIdx.x;   // 0..63
    const int sp  = blockIdx.y;   // 0..SPLITK-1
    const int n0  = nb * TN;
    const int m0  = sp * KCHUNK;

    // fragment lane mapping (PTX m16n8k16 row.col)
    const int rg = lid >> 2;            // 0..7: row group / n column group
    const int kc = (lid & 3) << 1;      // k-pair offset 0,2,4,6

    const float* pa0 = A + (size_t)(n0 + 16 * wid + rg) * NN + m0 + kc;  // rows rg
    const float* pa1 = pa0 + 8 * (size_t)NN;                              // rows rg+8
    const float* pb  = B + (size_t)rg * NN + m0 + kc;                     // n = rg (+8j)

    float c[4][4];
#pragma unroll
    for (int j = 0; j < 4; j++)
#pragma unroll
        for (int e = 0; e < 4; e++) c[j][e] = 0.0f;

#pragma unroll 2
    for (int k16 = 0; k16 < NK16; k16++) {
        const int ko = k16 * 16;

        // --- loads: 12 independent LDG.64 (front-batched by ptxas) ---
        float2 fa0 = *(const float2*)(pa0 + ko);
        float2 fa1 = *(const float2*)(pa1 + ko);
        float2 fa2 = *(const float2*)(pa0 + ko + 8);
        float2 fa3 = *(const float2*)(pa1 + ko + 8);
        float2 fb[8];
#pragma unroll
        for (int j = 0; j < 4; j++) {
            fb[2 * j]     = *(const float2*)(pb + (size_t)(8 * j) * NN + ko);
            fb[2 * j + 1] = *(const float2*)(pb + (size_t)(8 * j) * NN + ko + 8);
        }

        // --- convert to bf16 hi/lo ---
        uint32_t ah[4], al[4];
        split2(fa0.x, fa0.y, ah[0], al[0]);
        split2(fa1.x, fa1.y, ah[1], al[1]);
        split2(fa2.x, fa2.y, ah[2], al[2]);
        split2(fa3.x, fa3.y, ah[3], al[3]);
        uint32_t bh[8], bl[8];
#pragma unroll
        for (int i = 0; i < 8; i++) split2(fb[i].x, fb[i].y, bh[i], bl[i]);

        // --- 12 MMAs: hi*hi + hi*lo + lo*hi ---
#pragma unroll
        for (int j = 0; j < 4; j++) {
            mma16816(c[j][0], c[j][1], c[j][2], c[j][3],
                     ah[0], ah[1], ah[2], ah[3], bh[2 * j], bh[2 * j + 1]);
            mma16816(c[j][0], c[j][1], c[j][2], c[j][3],
                     ah[0], ah[1], ah[2], ah[3], bl[2 * j], bl[2 * j + 1]);
            mma16816(c[j][0], c[j][1], c[j][2], c[j][3],
                     al[0], al[1], al[2], al[3], bh[2 * j], bh[2 * j + 1]);
        }
    }

    // epilogue: thread holds (m = 16w + rg (+8), n = 8j + kc (+1))
    const int mg = n0 + 16 * wid + rg;
#pragma unroll
    for (int j = 0; j < 4; j++) {
        int r = 8 * j + kc;
        float* p0 = part + (size_t)(sp * RR + r) * NN + mg;
        float* p1 = part + (size_t)(sp * RR + r + 1) * NN + mg;
        p0[0] = c[j][0];
        p1[0] = c[j][1];
        p0[8] = c[j][2];
        p1[8] = c[j][3];
    }
}

// ---------------------------------------------------------------------------
// Reduce split-K partials into next z stage
// ---------------------------------------------------------------------------
__global__ void reduce_kernel(const float* __restrict__ part, float* __restrict__ out) {
    int idx = blockIdx.x * 256 + threadIdx.x;   // over 65536 float4
    const float4* p4 = (const float4*)part;
    float4 s = p4[idx];
#pragma unroll
    for (int sI = 1; sI < SPLITK; sI++) {
        float4 t = p4[idx + sI * (RR * NN / 4)];
        s.x += t.x; s.y += t.y; s.z += t.z; s.w += t.w;
    }
    ((float4*)out)[idx] = s;
}

// ---------------------------------------------------------------------------
// Final projection (torch-faithful raw-reshape mapping)
// ---------------------------------------------------------------------------
__global__ void final_kernel(const float* __restrict__ z, const float* __restrict__ W,
                             const float* __restrict__ bias, float* __restrict__ y) {
    __shared__ float Ws[256];
    __shared__ float bs[8];
    int t = threadIdx.x;
    Ws[t] = W[t];
    if (t < 8) bs[t] = bias[t];
    __syncthreads();

    int idx = blockIdx.x * 256 + t;
    int n = idx & (NN - 1);
    int b = idx >> 13;
    int k0 = n >> 11;
    int g0 = (n >> 8) & 7;
    const float* zp = z + ((size_t)(k0 * RR + b * 8 + g0) << 13) + ((n & 255) << 5);

    float bb = bs[n >> 10];
    float acc[8];
#pragma unroll
    for (int f = 0; f < 8; f++) acc[f] = bb;

#pragma unroll
    for (int jq = 0; jq < 8; jq++) {
        float4 zv = *(const float4*)(zp + 4 * jq);
#pragma unroll
        for (int e = 0; e < 4; e++) {
            float zs = (e == 0) ? zv.x : (e == 1) ? zv.y : (e == 2) ? zv.z : zv.w;
            int j = 4 * jq + e;
#pragma unroll
            for (int f = 0; f < 8; f++) acc[f] += zs * Ws[8 * j + f];
        }
    }

    float4* yo = (float4*)(y + (size_t)idx * 8);
    yo[0] = make_float4(acc[0], acc[1], acc[2], acc[3]);
    yo[1] = make_float4(acc[4], acc[5], acc[6], acc[7]);
}

// ---------------------------------------------------------------------------
extern "C" void kernel_launch(void* const* d_in, const int* in_sizes, int n_in,
                              void* d_out, int out_size) {
    const float* x    = (const float*)d_in[0];
    const float* S    = (const float*)d_in[1];
    const float* W    = (const float*)d_in[2];
    const float* bias = (const float*)d_in[3];
    float* y = (float*)d_out;

    float *zbuf, *pbuf;
    cudaGetSymbolAddress((void**)&zbuf, g_z);
    cudaGetSymbolAddress((void**)&pbuf, g_part);

    transpose_kernel<<<1024, 256>>>(x, zbuf);

    for (int k = 0; k < 3; k++) {
        gemm_kernel<<<dim3(64, SPLITK), 256>>>(S + (size_t)k * NN * NN,
                                               zbuf + (size_t)k * RR * NN, pbuf);
        reduce_kernel<<<256, 256>>>(pbuf, zbuf + (size_t)(k + 1) * RR * NN);
    }

    final_kernel<<<128, 256>>>(zbuf, W, bias, y);
}

// round 9
// speedup vs baseline: 1.8869x; 1.4929x over previous
#include <cuda_runtime.h>
#include <cuda_bf16.h>
#include <cstdint>

// Problem constants
#define NN 8192
#define RR 32
#define TN 128                    // M-tile per block
#define SPLITK 32
#define KCHUNK (NN / SPLITK)      // 256
#define NK16 (KCHUNK / 16)        // 16 k16-steps per CTA

// Scratch
__device__ float g_z[4 * RR * NN];          // z stages [k][r][n]
__device__ float g_part[SPLITK * RR * NN];  // split-K partials (32 MB)

// B smem: hi/lo bf16, [32 rows][256 k], row = 512B, XOR-16B swizzle by (n&7)
#define BROW_BYTES 512

__device__ __forceinline__ uint32_t cvt_bf16x2(float hi, float lo) {
    uint32_t r;
    asm("cvt.rn.bf16x2.f32 %0,%1,%2;" : "=r"(r) : "f"(hi), "f"(lo));
    return r;
}
// split 2 fp32 -> packed bf16 hi-pair and lo-pair (element x in low half)
__device__ __forceinline__ void split2(float x, float y, uint32_t& w, uint32_t& l) {
    w = cvt_bf16x2(y, x);
    float h0 = __uint_as_float(w << 16);
    float h1 = __uint_as_float(w & 0xFFFF0000u);
    l = cvt_bf16x2(y - h1, x - h0);
}
__device__ __forceinline__ void ldsm4(uint32_t& r0, uint32_t& r1, uint32_t& r2,
                                      uint32_t& r3, uint32_t a) {
    asm volatile("ldmatrix.sync.aligned.m8n8.x4.shared.b16 {%0,%1,%2,%3},[%4];"
                 : "=r"(r0), "=r"(r1), "=r"(r2), "=r"(r3) : "r"(a));
}
__device__ __forceinline__ void mma16816(float& c0, float& c1, float& c2, float& c3,
                                         uint32_t a0, uint32_t a1, uint32_t a2, uint32_t a3,
                                         uint32_t b0, uint32_t b1) {
    asm volatile(
        "mma.sync.aligned.m16n8k16.row.col.f32.bf16.bf16.f32 "
        "{%0,%1,%2,%3},{%4,%5,%6,%7},{%8,%9},{%0,%1,%2,%3};"
        : "+f"(c0), "+f"(c1), "+f"(c2), "+f"(c3)
        : "r"(a0), "r"(a1), "r"(a2), "r"(a3), "r"(b0), "r"(b1));
}

// ---------------------------------------------------------------------------
// Stage 0: transpose x[B,N,G] -> z0[r][n], r = b*8+g
// ---------------------------------------------------------------------------
__global__ void transpose_kernel(const float* __restrict__ x, float* __restrict__ z0) {
    int idx = blockIdx.x * 256 + threadIdx.x;
    int n = idx & (NN - 1);
    int r = idx >> 13;
    int b = r >> 3;
    int g = r & 7;
    z0[idx] = x[((b << 13) + n) * 8 + g];
}

// ---------------------------------------------------------------------------
// bf16x3 mma.sync GEMM:
//   part[sp][r][n0+m] = sum_{k in chunk} S[n0+m][k] * z[r][k]
// A fragments direct-LDG from global (as R7, verified); B pre-split into
// smem bf16 hi/lo ONCE per CTA, read via swizzled ldmatrix. No barriers in
// the main loop.
// ---------------------------------------------------------------------------
__global__ void __launch_bounds__(256, 4)
gemm_kernel(const float* __restrict__ A, const float* __restrict__ B,
            float* __restrict__ part) {
    __shared__ __align__(128) char smBH[RR * BROW_BYTES];   // 16 KB
    __shared__ __align__(128) char smBL[RR * BROW_BYTES];   // 16 KB

    const int tid = threadIdx.x;
    const int wid = tid >> 5;
    const int lid = tid & 31;
    const int nb  = blockIdx.x;   // 0..63
    const int sp  = blockIdx.y;   // 0..SPLITK-1
    const int n0  = nb * TN;
    const int m0  = sp * KCHUNK;

    // ---------------- one-time B staging: fp32 -> bf16 hi/lo smem ----------
    {
        const int row   = tid >> 3;          // 0..31
        const int kbase = (tid & 7) << 3;    // 0..56 step 8
        const float* bp = B + (size_t)row * NN + m0 + kbase;
        const uint32_t ph = ((uint32_t)row & 7u) << 4;   // 16B-granule XOR phase
#pragma unroll
        for (int i = 0; i < 4; i++) {
            const int k = kbase + 64 * i;
            float4 v0 = *(const float4*)(bp + 64 * i);
            float4 v1 = *(const float4*)(bp + 64 * i + 4);
            uint32_t h0, l0, h1, l1, h2, l2, h3, l3;
            split2(v0.x, v0.y, h0, l0);
            split2(v0.z, v0.w, h1, l1);
            split2(v1.x, v1.y, h2, l2);
            split2(v1.z, v1.w, h3, l3);
            uint32_t off = (uint32_t)row * BROW_BYTES + (((uint32_t)k * 2u) ^ ph);
            *(uint4*)(smBH + off) = make_uint4(h0, h1, h2, h3);
            *(uint4*)(smBL + off) = make_uint4(l0, l1, l2, l3);
        }
    }
    __syncthreads();   // the ONLY barrier

    // ---------------- fragment lane mappings --------------------------------
    // A (direct LDG, verified in R7): lane provides rows rg, rg+8 and k pairs
    const int rg = lid >> 2;            // 0..7
    const int kc = (lid & 3) << 1;      // 0,2,4,6
    const float* pa0 = A + (size_t)(n0 + 16 * wid + rg) * NN + m0 + kc;
    const float* pa1 = pa0 + 8 * (size_t)NN;

    // B ldmatrix (verified in R6): brow/bhalf lane mapping
    const int brow0 = ((lid >> 4) << 3) + (lid & 7);   // n-tiles 0/1
    const int brow1 = 16 + brow0;                      // n-tiles 2/3
    const int bhalf = (lid >> 3) & 1;
    const uint32_t smbh = (uint32_t)__cvta_generic_to_shared(smBH);
    const uint32_t smbl = (uint32_t)__cvta_generic_to_shared(smBL);
    const uint32_t bo0base = (uint32_t)brow0 * BROW_BYTES;
    const uint32_t bo1base = (uint32_t)brow1 * BROW_BYTES;
    const uint32_t bph0 = ((uint32_t)brow0 & 7u) << 4;
    const uint32_t bph1 = ((uint32_t)brow1 & 7u) << 4;

    float c[4][4];
#pragma unroll
    for (int j = 0; j < 4; j++)
#pragma unroll
        for (int e = 0; e < 4; e++) c[j][e] = 0.0f;

#pragma unroll 2
    for (int k16 = 0; k16 < NK16; k16++) {
        const int ko = k16 * 16;

        // A loads: 4 independent LDG.64
        float2 fa0 = *(const float2*)(pa0 + ko);
        float2 fa1 = *(const float2*)(pa1 + ko);
        float2 fa2 = *(const float2*)(pa0 + ko + 8);
        float2 fa3 = *(const float2*)(pa1 + ko + 8);

        // B fragments from smem (hi + lo), swizzled ldmatrix
        const uint32_t kb = (uint32_t)(k16 * 32 + bhalf * 16);
        const uint32_t o0 = bo0base + (kb ^ bph0);
        const uint32_t o1 = bo1base + (kb ^ bph1);
        uint32_t bh[8], bl[8];
        ldsm4(bh[0], bh[1], bh[2], bh[3], smbh + o0);
        ldsm4(bh[4], bh[5], bh[6], bh[7], smbh + o1);
        ldsm4(bl[0], bl[1], bl[2], bl[3], smbl + o0);
        ldsm4(bl[4], bl[5], bl[6], bl[7], smbl + o1);

        // A convert
        uint32_t ah[4], al[4];
        split2(fa0.x, fa0.y, ah[0], al[0]);
        split2(fa1.x, fa1.y, ah[1], al[1]);
        split2(fa2.x, fa2.y, ah[2], al[2]);
        split2(fa3.x, fa3.y, ah[3], al[3]);

        // 12 MMAs: hi*hi + hi*lo + lo*hi
#pragma unroll
        for (int j = 0; j < 4; j++) {
            mma16816(c[j][0], c[j][1], c[j][2], c[j][3],
                     ah[0], ah[1], ah[2], ah[3], bh[2 * j], bh[2 * j + 1]);
            mma16816(c[j][0], c[j][1], c[j][2], c[j][3],
                     ah[0], ah[1], ah[2], ah[3], bl[2 * j], bl[2 * j + 1]);
            mma16816(c[j][0], c[j][1], c[j][2], c[j][3],
                     al[0], al[1], al[2], al[3], bh[2 * j], bh[2 * j + 1]);
        }
    }

    // epilogue: thread holds (m = 16w + rg (+8), n = 8j + kc (+1))
    const int mg = n0 + 16 * wid + rg;
#pragma unroll
    for (int j = 0; j < 4; j++) {
        int r = 8 * j + kc;
        float* p0 = part + (size_t)(sp * RR + r) * NN + mg;
        float* p1 = part + (size_t)(sp * RR + r + 1) * NN + mg;
        p0[0] = c[j][0];
        p1[0] = c[j][1];
        p0[8] = c[j][2];
        p1[8] = c[j][3];
    }
}

// ---------------------------------------------------------------------------
// Reduce split-K partials into next z stage
// ---------------------------------------------------------------------------
__global__ void reduce_kernel(const float* __restrict__ part, float* __restrict__ out) {
    int idx = blockIdx.x * 256 + threadIdx.x;   // over 65536 float4
    const float4* p4 = (const float4*)part;
    float4 s = p4[idx];
#pragma unroll
    for (int sI = 1; sI < SPLITK; sI++) {
        float4 t = p4[idx + sI * (RR * NN / 4)];
        s.x += t.x; s.y += t.y; s.z += t.z; s.w += t.w;
    }
    ((float4*)out)[idx] = s;
}

// ---------------------------------------------------------------------------
// Final projection (torch-faithful raw-reshape mapping)
// ---------------------------------------------------------------------------
__global__ void final_kernel(const float* __restrict__ z, const float* __restrict__ W,
                             const float* __restrict__ bias, float* __restrict__ y) {
    __shared__ float Ws[256];
    __shared__ float bs[8];
    int t = threadIdx.x;
    Ws[t] = W[t];
    if (t < 8) bs[t] = bias[t];
    __syncthreads();

    int idx = blockIdx.x * 256 + t;
    int n = idx & (NN - 1);
    int b = idx >> 13;
    int k0 = n >> 11;
    int g0 = (n >> 8) & 7;
    const float* zp = z + ((size_t)(k0 * RR + b * 8 + g0) << 13) + ((n & 255) << 5);

    float bb = bs[n >> 10];
    float acc[8];
#pragma unroll
    for (int f = 0; f < 8; f++) acc[f] = bb;

#pragma unroll
    for (int jq = 0; jq < 8; jq++) {
        float4 zv = *(const float4*)(zp + 4 * jq);
#pragma unroll
        for (int e = 0; e < 4; e++) {
            float zs = (e == 0) ? zv.x : (e == 1) ? zv.y : (e == 2) ? zv.z : zv.w;
            int j = 4 * jq + e;
#pragma unroll
            for (int f = 0; f < 8; f++) acc[f] += zs * Ws[8 * j + f];
        }
    }

    float4* yo = (float4*)(y + (size_t)idx * 8);
    yo[0] = make_float4(acc[0], acc[1], acc[2], acc[3]);
    yo[1] = make_float4(acc[4], acc[5], acc[6], acc[7]);
}

// ---------------------------------------------------------------------------
extern "C" void kernel_launch(void* const* d_in, const int* in_sizes, int n_in,
                              void* d_out, int out_size) {
    const float* x    = (const float*)d_in[0];
    const float* S    = (const float*)d_in[1];
    const float* W    = (const float*)d_in[2];
    const float* bias = (const float*)d_in[3];
    float* y = (float*)d_out;

    float *zbuf, *pbuf;
    cudaGetSymbolAddress((void**)&zbuf, g_z);
    cudaGetSymbolAddress((void**)&pbuf, g_part);

    transpose_kernel<<<1024, 256>>>(x, zbuf);

    for (int k = 0; k < 3; k++) {
        gemm_kernel<<<dim3(64, SPLITK), 256>>>(S + (size_t)k * NN * NN,
                                               zbuf + (size_t)k * RR * NN, pbuf);
        reduce_kernel<<<256, 256>>>(pbuf, zbuf + (size_t)(k + 1) * RR * NN);
    }

    final_kernel<<<128, 256>>>(zbuf, W, bias, y);
}